// round 2
// baseline (speedup 1.0000x reference)
#include <cuda_runtime.h>
#include <cstdint>

#define FULLM 0xFFFFFFFFu
static constexpr int NDEPTH = 2;
static constexpr int NSIZE  = 1024;
static constexpr int NROWS  = 16384;
static constexpr int NCOEF  = 2046;   // sum of m for m=2..1024; factor m starts at offset m-2

// Repacked diag coefficients: for depth d, factor m, output block-position q (0..m-1):
// g_coef[d*NCOEF + (m-2) + q] = (M0.re, M0.im, M1.re, M1.im)
// where out[q] = M0 * in[low] + M1 * in[high]  (complex), low/high = q with bit (m/2) cleared/set.
__device__ float4 g_coef[NDEPTH * NCOEF];

__global__ void repack_kernel(const float* __restrict__ abcd){
  int idx = blockIdx.x * blockDim.x + threadIdx.x;
  if (idx >= NDEPTH * NCOEF) return;
  int d  = idx / NCOEF;
  int qg = idx - d * NCOEF;
  int v  = qg + 2;                     // in [2, 2048)
  int m  = 1 << (31 - __clz(v));       // factor size
  int q  = v - m;                      // position within factor, 0..m-1
  int off = 4096 - 4 * m;              // offset of this factor inside abcd[d]
  int half = m >> 1;
  int ih = (q >= half) ? 1 : 0;
  int k  = q - ih * half;
  const float* base = abcd + (size_t)d * 4092 * 2;
  int i0 = off + ih * m + k;           // M[ih][0][k]
  int i1 = i0 + half;                  // M[ih][1][k]
  g_coef[idx] = make_float4(base[2*i0], base[2*i0+1], base[2*i1], base[2*i1+1]);
}

__device__ __forceinline__ float mixf(float a, float b, float p){ return fmaf(p, b - a, a); }

__device__ __forceinline__ float2 cmix(float4 c, float2 u, float2 v){
  // out = (c.x + i c.y) * u + (c.z + i c.w) * v
  float2 o;
  o.x = c.x*u.x - c.y*u.y + c.z*v.x - c.w*v.y;
  o.y = c.x*u.y + c.y*u.x + c.z*v.y + c.w*v.x;
  return o;
}

// ---------------- perm factors, m <= 32 (register-local) ----------------
template<int M>
__device__ __forceinline__ void perm_local_r(float* s, float* t, float p0, float p1, float p2){
#pragma unroll
  for (int g = 0; g < 32; g += M)
#pragma unroll
    for (int j = 0; j < M; j++){
      int sj = (j < M/2) ? 2*j : 2*j - M + 1;          // even/odd gather (rotl)
      t[g+j] = mixf(s[g+j], s[g+sj], p0);
    }
#pragma unroll
  for (int g = 0; g < 32; g += M)
#pragma unroll
    for (int j = 0; j < M; j++){
      int pj = (j & (M/2)) | ((M/2 - 1) & ~j);         // half-reversal partner
      s[g+j] = mixf(t[g+j], t[g+pj], (j < M/2) ? p1 : p2);
    }
}

template<int M>
__device__ __forceinline__ void perm_local_c(float2* s, float2* t, float p0, float p1, float p2){
#pragma unroll
  for (int g = 0; g < 32; g += M)
#pragma unroll
    for (int j = 0; j < M; j++){
      int sj = (j < M/2) ? 2*j : 2*j - M + 1;
      t[g+j].x = mixf(s[g+j].x, s[g+sj].x, p0);
      t[g+j].y = mixf(s[g+j].y, s[g+sj].y, p0);
    }
#pragma unroll
  for (int g = 0; g < 32; g += M)
#pragma unroll
    for (int j = 0; j < M; j++){
      int pj = (j & (M/2)) | ((M/2 - 1) & ~j);
      float p = (j < M/2) ? p1 : p2;
      s[g+j].x = mixf(t[g+j].x, t[g+pj].x, p);
      s[g+j].y = mixf(t[g+j].y, t[g+pj].y, p);
    }
}

// ---------------- perm factors, m >= 64 (warp shuffles) ----------------
// layout: element i = lane*32 + r.  eo = rotate-left of low log2(M) bits of i:
//   src_reg  = (2r + msb) & 31, msb = bit (log2(M)-6) of lane-within-block's top bit
//   src_lane = blockbase | 2*(Llow mod M/64) + (r>=16)
// rev = complement of low (log2(M)-1) bits: reg -> 31-r, lane XOR (M/64 - 1).
template<int M>
__device__ __forceinline__ void perm_shfl_r(float* s, float* t, int lane, float p0, float p1, float p2){
  constexpr int LB = M/32;    // lanes per block
  constexpr int T  = M/64;    // MSB of lane-within-block
  int Llow = lane & (LB - 1);
  bool msb = (Llow & T) != 0;
  int slb = (lane & ~(LB - 1)) | (2 * (Llow & (T - 1)));
#pragma unroll
  for (int r = 0; r < 32; r++){
    int sl = slb + (r >> 4);
    float v0 = __shfl_sync(FULLM, s[(2*r) & 31], sl);
    float v1 = __shfl_sync(FULLM, s[(2*r+1) & 31], sl);
    t[r] = mixf(s[r], msb ? v1 : v0, p0);
  }
  constexpr int RM = M/64 - 1;
  float ps = (lane & (M/64)) ? p2 : p1;
#pragma unroll
  for (int r = 0; r < 32; r++){
    float pv = __shfl_xor_sync(FULLM, t[31 - r], RM);
    s[r] = mixf(t[r], pv, ps);
  }
}

template<int M>
__device__ __forceinline__ void perm_shfl_c(float2* s, float2* t, int lane, float p0, float p1, float p2){
  constexpr int LB = M/32;
  constexpr int T  = M/64;
  int Llow = lane & (LB - 1);
  bool msb = (Llow & T) != 0;
  int slb = (lane & ~(LB - 1)) | (2 * (Llow & (T - 1)));
#pragma unroll
  for (int r = 0; r < 32; r++){
    int sl = slb + (r >> 4);
    float v0x = __shfl_sync(FULLM, s[(2*r) & 31].x, sl);
    float v0y = __shfl_sync(FULLM, s[(2*r) & 31].y, sl);
    float v1x = __shfl_sync(FULLM, s[(2*r+1) & 31].x, sl);
    float v1y = __shfl_sync(FULLM, s[(2*r+1) & 31].y, sl);
    t[r].x = mixf(s[r].x, msb ? v1x : v0x, p0);
    t[r].y = mixf(s[r].y, msb ? v1y : v0y, p0);
  }
  constexpr int RM = M/64 - 1;
  float ps = (lane & (M/64)) ? p2 : p1;
#pragma unroll
  for (int r = 0; r < 32; r++){
    float pvx = __shfl_xor_sync(FULLM, t[31 - r].x, RM);
    float pvy = __shfl_xor_sync(FULLM, t[31 - r].y, RM);
    s[r].x = mixf(t[r].x, pvx, ps);
    s[r].y = mixf(t[r].y, pvy, ps);
  }
}

// ---------------- diag factors ----------------
template<int M>   // M = 2..32: pairs are register-local; coefs uniform across lanes
__device__ __forceinline__ void diag_local_c(const float2* s, float2* t, const float4* __restrict__ C){
#pragma unroll
  for (int q = 0; q < M; q++){
    float4 c = __ldg(C + (M - 2) + q);
#pragma unroll
    for (int g = 0; g < 32; g += M){
      int lo = g + (q & (M/2 - 1));
      t[g + q] = cmix(c, s[lo], s[lo + M/2]);
    }
  }
}

template<int M>   // M = 64..1024: partner = lane XOR M/64, same reg
__device__ __forceinline__ void diag_shfl_c(const float2* s, float2* t, const float4* __restrict__ C, int lane){
  constexpr int LB = M/32;
  int qbase = (lane & (LB - 1)) << 5;
  bool hi = (lane & (LB/2)) != 0;
#pragma unroll
  for (int r = 0; r < 32; r++){
    float px = __shfl_xor_sync(FULLM, s[r].x, LB/2);
    float py = __shfl_xor_sync(FULLM, s[r].y, LB/2);
    float4 c = __ldg(C + (M - 2) + qbase + r);
    float2 own = s[r];
    float2 prt = make_float2(px, py);
    float2 u = hi ? prt : own;   // low-half element
    float2 v = hi ? own : prt;   // high-half element
    t[r] = cmix(c, u, v);
  }
}

// ---------------- main kernel: one warp per row ----------------
__global__ void __launch_bounds__(256) butterfly_main(
    const float* __restrict__ x, const float* __restrict__ perm_logit,
    const float* __restrict__ bvec, float* __restrict__ out)
{
  int gwarp = (blockIdx.x * blockDim.x + threadIdx.x) >> 5;
  int lane  = threadIdx.x & 31;
  if (gwarp >= NROWS) return;

  float pa[3], pb[3];
#pragma unroll
  for (int j = 0; j < 3; j++){
    pa[j] = 1.0f / (1.0f + expf(-perm_logit[j]));
    pb[j] = 1.0f / (1.0f + expf(-perm_logit[3 + j]));
  }

  const float* xr = x + (size_t)gwarp * NSIZE + lane * 32;
  float ra[32], rb[32];
#pragma unroll
  for (int v = 0; v < 8; v++){
    float4 t = __ldg(reinterpret_cast<const float4*>(xr) + v);
    ra[4*v+0] = t.x; ra[4*v+1] = t.y; ra[4*v+2] = t.z; ra[4*v+3] = t.w;
  }

  // ---- depth 0: perm chain on REAL data only (imag is exactly 0) ----
  perm_local_r<4 >(ra, rb, pa[0], pa[1], pa[2]);
  perm_local_r<8 >(ra, rb, pa[0], pa[1], pa[2]);
  perm_local_r<16>(ra, rb, pa[0], pa[1], pa[2]);
  perm_local_r<32>(ra, rb, pa[0], pa[1], pa[2]);
  perm_shfl_r<64  >(ra, rb, lane, pa[0], pa[1], pa[2]);
  perm_shfl_r<128 >(ra, rb, lane, pa[0], pa[1], pa[2]);
  perm_shfl_r<256 >(ra, rb, lane, pa[0], pa[1], pa[2]);
  perm_shfl_r<512 >(ra, rb, lane, pa[0], pa[1], pa[2]);
  perm_shfl_r<1024>(ra, rb, lane, pa[0], pa[1], pa[2]);
  // result in ra

  const float4* C0 = g_coef;
  const float4* C1 = g_coef + NCOEF;

  float2 va[32], vb[32];
  {  // first diag factor (m=2), real input -> complex output
    float4 c0 = __ldg(C0 + 0);
    float4 c1 = __ldg(C0 + 1);
#pragma unroll
    for (int g = 0; g < 32; g += 2){
      float x0 = ra[g], x1 = ra[g+1];
      va[g]   = make_float2(c0.x*x0 + c0.z*x1, c0.y*x0 + c0.w*x1);
      va[g+1] = make_float2(c1.x*x0 + c1.z*x1, c1.y*x0 + c1.w*x1);
    }
  }
  diag_local_c<4 >(va, vb, C0);
  diag_local_c<8 >(vb, va, C0);
  diag_local_c<16>(va, vb, C0);
  diag_local_c<32>(vb, va, C0);
  diag_shfl_c<64  >(va, vb, C0, lane);
  diag_shfl_c<128 >(vb, va, C0, lane);
  diag_shfl_c<256 >(va, vb, C0, lane);
  diag_shfl_c<512 >(vb, va, C0, lane);
  diag_shfl_c<1024>(va, vb, C0, lane);
  // result in vb

  // ---- depth 1: complex perm chain (each factor leaves result in vb) ----
  perm_local_c<4 >(vb, va, pb[0], pb[1], pb[2]);
  perm_local_c<8 >(vb, va, pb[0], pb[1], pb[2]);
  perm_local_c<16>(vb, va, pb[0], pb[1], pb[2]);
  perm_local_c<32>(vb, va, pb[0], pb[1], pb[2]);
  perm_shfl_c<64  >(vb, va, lane, pb[0], pb[1], pb[2]);
  perm_shfl_c<128 >(vb, va, lane, pb[0], pb[1], pb[2]);
  perm_shfl_c<256 >(vb, va, lane, pb[0], pb[1], pb[2]);
  perm_shfl_c<512 >(vb, va, lane, pb[0], pb[1], pb[2]);
  perm_shfl_c<1024>(vb, va, lane, pb[0], pb[1], pb[2]);
  // result in vb

  diag_local_c<2 >(vb, va, C1);
  diag_local_c<4 >(va, vb, C1);
  diag_local_c<8 >(vb, va, C1);
  diag_local_c<16>(va, vb, C1);
  diag_local_c<32>(vb, va, C1);
  diag_shfl_c<64  >(va, vb, C1, lane);
  diag_shfl_c<128 >(vb, va, C1, lane);
  diag_shfl_c<256 >(va, vb, C1, lane);
  diag_shfl_c<512 >(vb, va, C1, lane);
  diag_shfl_c<1024>(va, vb, C1, lane);
  // result in vb

  const float* br = bvec + lane * 32;
  float* orow = out + (size_t)gwarp * NSIZE + lane * 32;
#pragma unroll
  for (int v = 0; v < 8; v++){
    float4 bb = __ldg(reinterpret_cast<const float4*>(br) + v);
    float4 o = make_float4(bb.x + vb[4*v+0].x, bb.y + vb[4*v+1].x,
                           bb.z + vb[4*v+2].x, bb.w + vb[4*v+3].x);
    reinterpret_cast<float4*>(orow)[v] = o;
  }
}

extern "C" void kernel_launch(void* const* d_in, const int* in_sizes, int n_in,
                              void* d_out, int out_size)
{
  const float* x          = (const float*)d_in[0];
  const float* perm_logit = (const float*)d_in[1];
  const float* abcd       = (const float*)d_in[2];
  const float* b          = (const float*)d_in[3];
  float* out = (float*)d_out;

  repack_kernel<<<(NDEPTH * NCOEF + 255) / 256, 256>>>(abcd);
  butterfly_main<<<NROWS / 8, 256>>>(x, perm_logit, b, out);
}

// round 4
// speedup vs baseline: 2.1088x; 2.1088x over previous
#include <cuda_runtime.h>
#include <cstdint>

#define FULLM 0xFFFFFFFFu
static constexpr int NDEPTH = 2;
static constexpr int NSIZE  = 1024;
static constexpr int NROWS  = 16384;
static constexpr int NCOEF  = 2046;   // sum of m for m=2..1024; factor m at offset m-2

// Diag coefs, natural layout (used by register-local factors, m<=32):
//   g_coef[d*NCOEF + (m-2) + q] = (M0.re, M0.im, M1.re, M1.im)
//   out[q] = M0*in[lo] + M1*in[hi], lo/hi = q with bit m/2 cleared/set.
__device__ float4 g_coef [NDEPTH * NCOEF];
// Transposed layout for shuffle factors (m>=64): entry for position q=(Llow<<5)+r
// stored at (m-2) + r*LB + Llow  (LB = m/32) so a warp's 32 lanes read
// LB consecutive float4s (broadcast/coalesced) instead of 32 distinct lines.
__device__ float4 g_coefT[NDEPTH * NCOEF];

__global__ void repack_kernel(const float* __restrict__ abcd){
  int idx = blockIdx.x * blockDim.x + threadIdx.x;
  if (idx >= NDEPTH * NCOEF) return;
  int d  = idx / NCOEF;
  int qg = idx - d * NCOEF;
  int v  = qg + 2;                     // in [2, 2048)
  int m  = 1 << (31 - __clz(v));       // factor size
  int q  = v - m;                      // position within factor, 0..m-1
  int off = 4096 - 4 * m;              // offset of this factor inside abcd[d]
  int half = m >> 1;
  int ih = (q >= half) ? 1 : 0;
  int k  = q - ih * half;
  const float* base = abcd + (size_t)d * 4092 * 2;
  int i0 = off + ih * m + k;           // M[ih][0][k]
  int i1 = i0 + half;                  // M[ih][1][k]
  float4 val = make_float4(base[2*i0], base[2*i0+1], base[2*i1], base[2*i1+1]);
  g_coef[idx] = val;
  int LB = m / 32;
  int tpos = (m >= 64) ? ((q & 31) * LB + (q >> 5)) : q;
  g_coefT[d * NCOEF + (m - 2) + tpos] = val;
}

__device__ __forceinline__ float mixf(float a, float b, float p){ return fmaf(p, b - a, a); }

// ---------------- real perm factor, m <= 32 (register-local), in s -> out s ----
template<int M>
__device__ __forceinline__ void perm_local(float* s, float* t, float p0, float p1, float p2){
#pragma unroll
  for (int g = 0; g < 32; g += M)
#pragma unroll
    for (int j = 0; j < M; j++){
      int sj = (j < M/2) ? 2*j : 2*j - M + 1;          // even/odd gather (rotl)
      t[g+j] = mixf(s[g+j], s[g+sj], p0);
    }
#pragma unroll
  for (int g = 0; g < 32; g += M)
#pragma unroll
    for (int j = 0; j < M; j++){
      int pj = (j & (M/2)) | ((M/2 - 1) & ~j);         // half-reversal partner
      s[g+j] = mixf(t[g+j], t[g+pj], (j < M/2) ? p1 : p2);
    }
}

// ---------------- real perm factor, m >= 64 (warp shuffles), in s -> out s -----
// eo with ONE shuffle per register:
//   msb0 lanes handle r=k at step k (reg e=(2k)&31 from slb+kk);
//   msb1 lanes handle r=k^16 at step k (reg e|1 from slb+1-kk).
//   At a kk-step, lanes with parity==kk publish s[e], others s[e|1]; every
//   shuffle delivers a useful value to every dest lane.
template<int M>
__device__ __forceinline__ void perm_shfl_1(float* s, float* t, int lane, float p0, float p1, float p2){
  constexpr int LB = M/32;    // lanes per block
  constexpr int T  = M/64;    // msb bit of lane-within-block
  int Llow = lane & (LB - 1);
  int msb  = (Llow & T) ? 1 : 0;
  int slb  = (lane & ~(LB - 1)) | (2 * (Llow & (T - 1)));
  int sl0  = slb + msb;        // source lane for kk=0 steps
  int sl1  = slb + 1 - msb;    // source lane for kk=1 steps
  bool le  = (lane & 1) == 0;
#pragma unroll
  for (int k = 0; k < 16; k++){
    const int e = (2*k) & 31;
    float u1 = le ? s[e] : s[e|1];                       // kk=0 publish
    float v1 = (M == 64) ? u1 : __shfl_sync(FULLM, u1, sl0);  // M=64: sl0==lane
    float u2 = le ? s[e|1] : s[e];                       // kk=1 publish
    float v2 = __shfl_sync(FULLM, u2, sl1);
    float a = msb ? v2 : v1;
    float b = msb ? v1 : v2;
    t[k]    = mixf(s[k],    a, p0);
    t[k+16] = mixf(s[k+16], b, p0);
  }
  // rev: complement of low log2(M)-1 bits -> reg 31-r, lane XOR (M/64-1)
  constexpr int RM = T - 1;
  float ps = (lane & T) ? p2 : p1;
  if (RM == 0){
#pragma unroll
    for (int r = 0; r < 16; r++){
      float x0 = t[r], x1 = t[31-r];
      s[r]    = mixf(x0, x1, ps);
      s[31-r] = mixf(x1, x0, ps);
    }
  } else {
#pragma unroll
    for (int r = 0; r < 32; r++){
      float pv = __shfl_xor_sync(FULLM, t[31-r], RM);
      s[r] = mixf(t[r], pv, ps);
    }
  }
}

__device__ __forceinline__ void perm_chain(float* s, float* t, int lane, const float* p){
  perm_local<4 >(s, t, p[0], p[1], p[2]);
  perm_local<8 >(s, t, p[0], p[1], p[2]);
  perm_local<16>(s, t, p[0], p[1], p[2]);
  perm_local<32>(s, t, p[0], p[1], p[2]);
  perm_shfl_1<64  >(s, t, lane, p[0], p[1], p[2]);
  perm_shfl_1<128 >(s, t, lane, p[0], p[1], p[2]);
  perm_shfl_1<256 >(s, t, lane, p[0], p[1], p[2]);
  perm_shfl_1<512 >(s, t, lane, p[0], p[1], p[2]);
  perm_shfl_1<1024>(s, t, lane, p[0], p[1], p[2]);
}

// ---------------- diag factors, fully in-place ----------------
template<int M>   // M = 2..32: pairs register-local; coefs uniform (broadcast)
__device__ __forceinline__ void diag_local_ip(float* sx, float* sy, const float4* __restrict__ C){
#pragma unroll
  for (int q = 0; q < M/2; q++){
    float4 clo = __ldg(C + (M - 2) + q);
    float4 chi = __ldg(C + (M - 2) + q + M/2);
#pragma unroll
    for (int g = 0; g < 32; g += M){
      int lo = g + q, hi = lo + M/2;
      float ur = sx[lo], ui = sy[lo], vr = sx[hi], vi = sy[hi];
      sx[lo] = clo.x*ur - clo.y*ui + clo.z*vr - clo.w*vi;
      sy[lo] = clo.x*ui + clo.y*ur + clo.z*vi + clo.w*vr;
      sx[hi] = chi.x*ur - chi.y*ui + chi.z*vr - chi.w*vi;
      sy[hi] = chi.x*ui + chi.y*ur + chi.z*vi + chi.w*vr;
    }
  }
}

template<int M>   // M = 64..1024: partner = lane XOR M/64, same reg; transposed coefs
__device__ __forceinline__ void diag_shfl_ip(float* sx, float* sy, const float4* __restrict__ CT, int lane){
  constexpr int LB = M/32;
  int Llow = lane & (LB - 1);
  bool hi = (lane & (LB/2)) != 0;
#pragma unroll
  for (int r = 0; r < 32; r++){
    float px = __shfl_xor_sync(FULLM, sx[r], LB/2);
    float py = __shfl_xor_sync(FULLM, sy[r], LB/2);
    float4 c = __ldg(CT + (M - 2) + r * LB + Llow);
    float ox = sx[r], oy = sy[r];
    float ur = hi ? px : ox, ui = hi ? py : oy;   // low-half element
    float vr = hi ? ox : px, vi = hi ? oy : py;   // high-half element
    sx[r] = c.x*ur - c.y*ui + c.z*vr - c.w*vi;
    sy[r] = c.x*ui + c.y*ur + c.z*vi + c.w*vr;
  }
}

// ---------------- main kernel: one warp per row ----------------
__global__ void __launch_bounds__(128, 3) butterfly_main(
    const float* __restrict__ x, const float* __restrict__ perm_logit,
    const float* __restrict__ bvec, float* __restrict__ out)
{
  int gwarp = (blockIdx.x * blockDim.x + threadIdx.x) >> 5;
  int lane  = threadIdx.x & 31;
  if (gwarp >= NROWS) return;

  float pa[3], pb[3];
#pragma unroll
  for (int j = 0; j < 3; j++){
    pa[j] = 1.0f / (1.0f + __expf(-perm_logit[j]));
    pb[j] = 1.0f / (1.0f + __expf(-perm_logit[3 + j]));
  }

  float sx[32], sy[32], tt[32];
  const float* xr = x + (size_t)gwarp * NSIZE + lane * 32;
#pragma unroll
  for (int v = 0; v < 8; v++){
    float4 t = __ldg(reinterpret_cast<const float4*>(xr) + v);
    sx[4*v+0] = t.x; sx[4*v+1] = t.y; sx[4*v+2] = t.z; sx[4*v+3] = t.w;
  }

  const float4* C0  = g_coef;
  const float4* C1  = g_coef  + NCOEF;
  const float4* C0T = g_coefT;
  const float4* C1T = g_coefT + NCOEF;

  // ---- depth 0: perm chain on REAL data only (imag is exactly 0) ----
  perm_chain(sx, tt, lane, pa);

  // first diag factor (m=2): real input -> complex output, in-place
  {
    float4 c0 = __ldg(C0 + 0);
    float4 c1 = __ldg(C0 + 1);
#pragma unroll
    for (int g = 0; g < 32; g += 2){
      float x0 = sx[g], x1 = sx[g+1];
      sx[g]   = c0.x*x0 + c0.z*x1;  sy[g]   = c0.y*x0 + c0.w*x1;
      sx[g+1] = c1.x*x0 + c1.z*x1;  sy[g+1] = c1.y*x0 + c1.w*x1;
    }
  }
  diag_local_ip<4 >(sx, sy, C0);
  diag_local_ip<8 >(sx, sy, C0);
  diag_local_ip<16>(sx, sy, C0);
  diag_local_ip<32>(sx, sy, C0);
  diag_shfl_ip<64  >(sx, sy, C0T, lane);
  diag_shfl_ip<128 >(sx, sy, C0T, lane);
  diag_shfl_ip<256 >(sx, sy, C0T, lane);
  diag_shfl_ip<512 >(sx, sy, C0T, lane);
  diag_shfl_ip<1024>(sx, sy, C0T, lane);

  // ---- depth 1: perm chains per component (perm never mixes re/im) ----
  perm_chain(sx, tt, lane, pb);
  perm_chain(sy, tt, lane, pb);

  diag_local_ip<2 >(sx, sy, C1);
  diag_local_ip<4 >(sx, sy, C1);
  diag_local_ip<8 >(sx, sy, C1);
  diag_local_ip<16>(sx, sy, C1);
  diag_local_ip<32>(sx, sy, C1);
  diag_shfl_ip<64  >(sx, sy, C1T, lane);
  diag_shfl_ip<128 >(sx, sy, C1T, lane);
  diag_shfl_ip<256 >(sx, sy, C1T, lane);
  diag_shfl_ip<512 >(sx, sy, C1T, lane);
  diag_shfl_ip<1024>(sx, sy, C1T, lane);

  const float* br = bvec + lane * 32;
  float* orow = out + (size_t)gwarp * NSIZE + lane * 32;
#pragma unroll
  for (int v = 0; v < 8; v++){
    float4 bb = __ldg(reinterpret_cast<const float4*>(br) + v);
    float4 o = make_float4(bb.x + sx[4*v+0], bb.y + sx[4*v+1],
                           bb.z + sx[4*v+2], bb.w + sx[4*v+3]);
    reinterpret_cast<float4*>(orow)[v] = o;
  }
}

extern "C" void kernel_launch(void* const* d_in, const int* in_sizes, int n_in,
                              void* d_out, int out_size)
{
  const float* x          = (const float*)d_in[0];
  const float* perm_logit = (const float*)d_in[1];
  const float* abcd       = (const float*)d_in[2];
  const float* b          = (const float*)d_in[3];
  float* out = (float*)d_out;

  repack_kernel<<<(NDEPTH * NCOEF + 255) / 256, 256>>>(abcd);
  butterfly_main<<<NROWS / 4, 128>>>(x, perm_logit, b, out);
}